// round 13
// baseline (speedup 1.0000x reference)
#include <cuda_runtime.h>
#include <cuda_bf16.h>
#include <cstdint>

// Fan-model nonlinear mixing via mma.sync bf16 (R11 lineage):
//   out[b,x] = L + (L^2 - Q)/2,  L = sum_p E[b,p] a[p,x],  Q = sum_p E^2 a^2
// bf16 hi/lo split, K stacked (al*el dropped).
// R13: 64 px/warp, warp-private transpose buffer (pitch 68, conflict-free),
// output written by cp.async.bulk S2G (256B per band row) issued by lanes
// 0-7, double-buffered, __syncwarp-only. B-frag tables read via __ldg
// (L1-resident) -> no CTA smem tables, no __syncthreads anywhere.

#define NPIX (512 * 512)
#define NP   12
#define NB   224
#define NOCT (NB / 8)            // 28

#define PITCH_W 68                        // floats per band row (64 + 4 pad)
#define WBUF_BYTES (8 * PITCH_W * 4)      // 2176 per slot
#define SM_TOTAL (4 * 2 * WBUF_BYTES)     // 4 warps x 2 slots = 17408

// fragment-order B tables: [mat][octet][lane] = uint4 {b0,b1,lo0,lo1}
__device__ __align__(16) uint4 g_tbl[2][NOCT][32];

static __device__ __forceinline__ uint32_t pk(float lo, float hi) {
    uint32_t r;
    asm("cvt.rn.bf16x2.f32 %0, %1, %2;" : "=r"(r) : "f"(hi), "f"(lo));
    return r;
}

__global__ void prep_kernel(const float* __restrict__ E) {
    int idx = blockIdx.x * blockDim.x + threadIdx.x;
    if (idx >= NOCT * 32) return;
    int o = idx >> 5, t = idx & 31;
    int g = t >> 2, i = t & 3;
    int band = o * 8 + g;

    float eh[16], el[16], fh[16], fl[16];
#pragma unroll
    for (int p = 0; p < 16; p++) {
        float e = (p < NP) ? E[band * NP + p] : 0.0f;
        float f = e * e;
        float ehp = __bfloat162float(__float2bfloat16(e));
        float fhp = __bfloat162float(__float2bfloat16(f));
        eh[p] = e;  el[p] = e - ehp;
        fh[p] = f;  fl[p] = f - fhp;
    }
    uint4 ve, vf;
    ve.x = pk(eh[2 * i], eh[2 * i + 1]);
    ve.y = pk(eh[8 + 2 * i], eh[8 + 2 * i + 1]);
    ve.z = pk(el[2 * i], el[2 * i + 1]);
    ve.w = pk(el[8 + 2 * i], el[8 + 2 * i + 1]);
    vf.x = pk(fh[2 * i], fh[2 * i + 1]);
    vf.y = pk(fh[8 + 2 * i], fh[8 + 2 * i + 1]);
    vf.z = pk(fl[2 * i], fl[2 * i + 1]);
    vf.w = pk(fl[8 + 2 * i], fl[8 + 2 * i + 1]);
    g_tbl[0][o][t] = ve;
    g_tbl[1][o][t] = vf;
}

#define MMA(c0,c1,c2,c3,a0,a1,a2,a3,b0,b1) \
    asm volatile("mma.sync.aligned.m16n8k16.row.col.f32.bf16.bf16.f32 " \
        "{%0,%1,%2,%3}, {%4,%5,%6,%7}, {%8,%9}, {%0,%1,%2,%3};" \
        : "+f"(c0), "+f"(c1), "+f"(c2), "+f"(c3) \
        : "r"(a0), "r"(a1), "r"(a2), "r"(a3), "r"(b0), "r"(b1))

__global__ __launch_bounds__(128) void fm_mma_kernel(
    const float* __restrict__ A, float* __restrict__ out)
{
    extern __shared__ char sm[];
    uint32_t sbase;
    asm("{ .reg .u64 t; cvta.to.shared.u64 t, %1; cvt.u32.u64 %0, t; }"
        : "=r"(sbase) : "l"(sm));

    const int tid = threadIdx.x;
    const int t = tid & 31;
    const int w = tid >> 5;          // warp 0..3
    const int g = t >> 2;            // 0..7
    const int i = t & 3;             // 0..3
    const int pxw = blockIdx.x * 256 + w * 64;   // warp's first pixel

    // ---- A fragments for 4 M-tiles (built once) ----
    uint32_t aH[4][4], aL[4][4], sH[4][4], sL[4][4];
    const int p0 = 2 * i, p1 = 2 * i + 1;
    const int p2 = 2 * i + 8, p3 = 2 * i + 9;
#pragma unroll
    for (int m = 0; m < 4; m++) {
        const int pxA = pxw + 16 * m + g;
        const int pxB = pxA + 8;
        float vA0 = __ldg(A + (size_t)p0 * NPIX + pxA);
        float vA1 = __ldg(A + (size_t)p1 * NPIX + pxA);
        float vB0 = __ldg(A + (size_t)p0 * NPIX + pxB);
        float vB1 = __ldg(A + (size_t)p1 * NPIX + pxB);
        float vA2 = (i < 2) ? __ldg(A + (size_t)p2 * NPIX + pxA) : 0.0f;
        float vA3 = (i < 2) ? __ldg(A + (size_t)p3 * NPIX + pxA) : 0.0f;
        float vB2 = (i < 2) ? __ldg(A + (size_t)p2 * NPIX + pxB) : 0.0f;
        float vB3 = (i < 2) ? __ldg(A + (size_t)p3 * NPIX + pxB) : 0.0f;

#define SPLIT(v, h, l) float h = __bfloat162float(__float2bfloat16(v)); float l = (v) - h;
        SPLIT(vA0, hA0, lA0) SPLIT(vA1, hA1, lA1) SPLIT(vA2, hA2, lA2) SPLIT(vA3, hA3, lA3)
        SPLIT(vB0, hB0, lB0) SPLIT(vB1, hB1, lB1) SPLIT(vB2, hB2, lB2) SPLIT(vB3, hB3, lB3)
        float q0 = vA0 * vA0, q1 = vA1 * vA1, q2 = vA2 * vA2, q3 = vA3 * vA3;
        float u0 = vB0 * vB0, u1 = vB1 * vB1, u2 = vB2 * vB2, u3 = vB3 * vB3;
        SPLIT(q0, hq0, lq0) SPLIT(q1, hq1, lq1) SPLIT(q2, hq2, lq2) SPLIT(q3, hq3, lq3)
        SPLIT(u0, hu0, lu0) SPLIT(u1, hu1, lu1) SPLIT(u2, hu2, lu2) SPLIT(u3, hu3, lu3)

        aH[m][0] = pk(vA0, vA1); aH[m][1] = pk(vB0, vB1);
        aH[m][2] = pk(vA2, vA3); aH[m][3] = pk(vB2, vB3);
        aL[m][0] = pk(lA0, lA1); aL[m][1] = pk(lB0, lB1);
        aL[m][2] = pk(lA2, lA3); aL[m][3] = pk(lB2, lB3);
        sH[m][0] = pk(q0, q1);   sH[m][1] = pk(u0, u1);
        sH[m][2] = pk(q2, q3);   sH[m][3] = pk(u2, u3);
        sL[m][0] = pk(lq0, lq1); sL[m][1] = pk(lu0, lu1);
        sL[m][2] = pk(lq2, lq3); sL[m][3] = pk(lu2, lu3);
    }

    // ---- loop-invariant addresses ----
    const uint32_t wbuf = sbase + (uint32_t)w * (2 * WBUF_BYTES);
    // STS: band row 2i, pixel column g (banks 8i+g+c, conflict-free)
    const uint32_t st_b = wbuf + ((uint32_t)(2 * i) * PITCH_W + g) * 4;
    // bulk source for lanes<8: band row t at wbuf + t*272 (16B aligned)
    const uint32_t bsrc = wbuf + (uint32_t)t * (PITCH_W * 4);
    // bulk dst for lanes<8: band (o*8 + t), pixels [pxw, pxw+64)
    const float* gdst = out + (size_t)t * NPIX + pxw;

#pragma unroll 1
    for (int o = 0; o < NOCT; o++) {
        // B fragments straight from global (L1-resident after first pass)
        const uint4 ue = __ldg(&g_tbl[0][o][t]);
        const uint4 uf = __ldg(&g_tbl[1][o][t]);

        float r[4][4];
#pragma unroll
        for (int m = 0; m < 4; m++) {
            float cl0 = 0.f, cl1 = 0.f, cl2 = 0.f, cl3 = 0.f;
            float cq0 = 0.f, cq1 = 0.f, cq2 = 0.f, cq3 = 0.f;
            MMA(cl0, cl1, cl2, cl3, aH[m][0], aH[m][1], aH[m][2], aH[m][3], ue.x, ue.y);
            MMA(cl0, cl1, cl2, cl3, aL[m][0], aL[m][1], aL[m][2], aL[m][3], ue.x, ue.y);
            MMA(cl0, cl1, cl2, cl3, aH[m][0], aH[m][1], aH[m][2], aH[m][3], ue.z, ue.w);
            MMA(cq0, cq1, cq2, cq3, sH[m][0], sH[m][1], sH[m][2], sH[m][3], uf.x, uf.y);
            MMA(cq0, cq1, cq2, cq3, sL[m][0], sL[m][1], sL[m][2], sL[m][3], uf.x, uf.y);
            MMA(cq0, cq1, cq2, cq3, sH[m][0], sH[m][1], sH[m][2], sH[m][3], uf.z, uf.w);
            r[m][0] = fmaf(0.5f, fmaf(cl0, cl0, -cq0), cl0);  // (band 2i,   px g)
            r[m][1] = fmaf(0.5f, fmaf(cl1, cl1, -cq1), cl1);  // (band 2i+1, px g)
            r[m][2] = fmaf(0.5f, fmaf(cl2, cl2, -cq2), cl2);  // (band 2i,   px g+8)
            r[m][3] = fmaf(0.5f, fmaf(cl3, cl3, -cq3), cl3);  // (band 2i+1, px g+8)
        }

        // slot (o&1) was read by octet o-2's bulk group -> allow 1 pending
        if (o >= 2 && t < 8)
            asm volatile("cp.async.bulk.wait_group.read 1;" ::: "memory");
        __syncwarp();

        const uint32_t so = (uint32_t)(o & 1) * WBUF_BYTES;
#pragma unroll
        for (int m = 0; m < 4; m++) {
            const uint32_t sb = st_b + so + m * 64;   // +16 px per tile
            asm volatile("st.shared.f32 [%0], %1;" :: "r"(sb), "f"(r[m][0]));
            asm volatile("st.shared.f32 [%0], %1;" :: "r"(sb + PITCH_W * 4), "f"(r[m][1]));
            asm volatile("st.shared.f32 [%0], %1;" :: "r"(sb + 32), "f"(r[m][2]));
            asm volatile("st.shared.f32 [%0], %1;" :: "r"(sb + PITCH_W * 4 + 32), "f"(r[m][3]));
        }
        __syncwarp();
        asm volatile("fence.proxy.async.shared::cta;" ::: "memory");

        if (t < 8) {
            asm volatile(
                "cp.async.bulk.global.shared::cta.bulk_group [%0], [%1], 256;"
                :: "l"(gdst), "r"(bsrc + so) : "memory");
            asm volatile("cp.async.bulk.commit_group;" ::: "memory");
        }
        gdst += 8 * (size_t)NPIX;
    }
    // smem must stay valid until all bulk reads complete
    if (t < 8)
        asm volatile("cp.async.bulk.wait_group 0;" ::: "memory");
}

extern "C" void kernel_launch(void* const* d_in, const int* in_sizes, int n_in,
                              void* d_out, int out_size)
{
    const float* E = (const float*)d_in[0];
    const float* A = (const float*)d_in[1];
    if (in_sizes[0] > in_sizes[1]) {
        E = (const float*)d_in[1];
        A = (const float*)d_in[0];
    }
    float* out = (float*)d_out;

    cudaFuncSetAttribute(fm_mma_kernel,
                         cudaFuncAttributeMaxDynamicSharedMemorySize, SM_TOTAL);

    prep_kernel<<<7, 128>>>(E);
    fm_mma_kernel<<<NPIX / 256, 128, SM_TOTAL>>>(A, out);  // 1024 blocks
}

// round 14
// speedup vs baseline: 1.4029x; 1.4029x over previous
#include <cuda_runtime.h>
#include <cuda_bf16.h>
#include <cstdint>

// Fan-model nonlinear mixing via mma.sync bf16 (R11 lineage):
//   out[b,x] = L + (L^2 - Q)/2,  L = sum_p E[b,p] a[p,x],  Q = sum_p E^2 a^2
// bf16 hi/lo split, K stacked (al*el dropped).
// R14 = R11 (64 px/warp, warp-private conflict-free transpose, coalesced
// STG.128, no CTA barriers) with the B-fragment tables read via __ldg from
// global (L1-resident, same wavefront cost as LDS) instead of staged in
// smem: smem 37.4KB -> 8.7KB, residency 4 -> 5 CTAs/SM.

#define NPIX (512 * 512)
#define NP   12
#define NB   224
#define NOCT (NB / 8)            // 28

#define PITCH_W 68                        // floats per band row (64 + 4)
#define WBUF_BYTES (8 * PITCH_W * 4)      // 2176 per warp
#define SM_TOTAL (4 * WBUF_BYTES)         // 8704

// fragment-order B tables: [mat][octet][lane] = uint4 {b0,b1,lo0,lo1}
__device__ __align__(16) uint4 g_tbl[2][NOCT][32];

static __device__ __forceinline__ uint32_t pk(float lo, float hi) {
    uint32_t r;
    asm("cvt.rn.bf16x2.f32 %0, %1, %2;" : "=r"(r) : "f"(hi), "f"(lo));
    return r;
}

__global__ void prep_kernel(const float* __restrict__ E) {
    int idx = blockIdx.x * blockDim.x + threadIdx.x;
    if (idx >= NOCT * 32) return;
    int o = idx >> 5, t = idx & 31;
    int g = t >> 2, i = t & 3;
    int band = o * 8 + g;

    float eh[16], el[16], fh[16], fl[16];
#pragma unroll
    for (int p = 0; p < 16; p++) {
        float e = (p < NP) ? E[band * NP + p] : 0.0f;
        float f = e * e;
        float ehp = __bfloat162float(__float2bfloat16(e));
        float fhp = __bfloat162float(__float2bfloat16(f));
        eh[p] = e;  el[p] = e - ehp;
        fh[p] = f;  fl[p] = f - fhp;
    }
    uint4 ve, vf;
    ve.x = pk(eh[2 * i], eh[2 * i + 1]);
    ve.y = pk(eh[8 + 2 * i], eh[8 + 2 * i + 1]);
    ve.z = pk(el[2 * i], el[2 * i + 1]);
    ve.w = pk(el[8 + 2 * i], el[8 + 2 * i + 1]);
    vf.x = pk(fh[2 * i], fh[2 * i + 1]);
    vf.y = pk(fh[8 + 2 * i], fh[8 + 2 * i + 1]);
    vf.z = pk(fl[2 * i], fl[2 * i + 1]);
    vf.w = pk(fl[8 + 2 * i], fl[8 + 2 * i + 1]);
    g_tbl[0][o][t] = ve;
    g_tbl[1][o][t] = vf;
}

#define MMA(c0,c1,c2,c3,a0,a1,a2,a3,b0,b1) \
    asm volatile("mma.sync.aligned.m16n8k16.row.col.f32.bf16.bf16.f32 " \
        "{%0,%1,%2,%3}, {%4,%5,%6,%7}, {%8,%9}, {%0,%1,%2,%3};" \
        : "+f"(c0), "+f"(c1), "+f"(c2), "+f"(c3) \
        : "r"(a0), "r"(a1), "r"(a2), "r"(a3), "r"(b0), "r"(b1))

__global__ __launch_bounds__(128, 5) void fm_mma_kernel(
    const float* __restrict__ A, float* __restrict__ out)
{
    extern __shared__ char sm[];
    uint32_t sbase;
    asm("{ .reg .u64 t; cvta.to.shared.u64 t, %1; cvt.u32.u64 %0, t; }"
        : "=r"(sbase) : "l"(sm));

    const int tid = threadIdx.x;
    const int t = tid & 31;
    const int w = tid >> 5;          // warp 0..3
    const int g = t >> 2;            // 0..7
    const int i = t & 3;             // 0..3
    const int pxw = blockIdx.x * 256 + w * 64;   // warp's first pixel

    // ---- A fragments for 4 M-tiles (built once) ----
    uint32_t aH[4][4], aL[4][4], sH[4][4], sL[4][4];
    const int p0 = 2 * i, p1 = 2 * i + 1;
    const int p2 = 2 * i + 8, p3 = 2 * i + 9;
#pragma unroll
    for (int m = 0; m < 4; m++) {
        const int pxA = pxw + 16 * m + g;
        const int pxB = pxA + 8;
        float vA0 = __ldg(A + (size_t)p0 * NPIX + pxA);
        float vA1 = __ldg(A + (size_t)p1 * NPIX + pxA);
        float vB0 = __ldg(A + (size_t)p0 * NPIX + pxB);
        float vB1 = __ldg(A + (size_t)p1 * NPIX + pxB);
        float vA2 = (i < 2) ? __ldg(A + (size_t)p2 * NPIX + pxA) : 0.0f;
        float vA3 = (i < 2) ? __ldg(A + (size_t)p3 * NPIX + pxA) : 0.0f;
        float vB2 = (i < 2) ? __ldg(A + (size_t)p2 * NPIX + pxB) : 0.0f;
        float vB3 = (i < 2) ? __ldg(A + (size_t)p3 * NPIX + pxB) : 0.0f;

#define SPLIT(v, h, l) float h = __bfloat162float(__float2bfloat16(v)); float l = (v) - h;
        SPLIT(vA0, hA0, lA0) SPLIT(vA1, hA1, lA1) SPLIT(vA2, hA2, lA2) SPLIT(vA3, hA3, lA3)
        SPLIT(vB0, hB0, lB0) SPLIT(vB1, hB1, lB1) SPLIT(vB2, hB2, lB2) SPLIT(vB3, hB3, lB3)
        float q0 = vA0 * vA0, q1 = vA1 * vA1, q2 = vA2 * vA2, q3 = vA3 * vA3;
        float u0 = vB0 * vB0, u1 = vB1 * vB1, u2 = vB2 * vB2, u3 = vB3 * vB3;
        SPLIT(q0, hq0, lq0) SPLIT(q1, hq1, lq1) SPLIT(q2, hq2, lq2) SPLIT(q3, hq3, lq3)
        SPLIT(u0, hu0, lu0) SPLIT(u1, hu1, lu1) SPLIT(u2, hu2, lu2) SPLIT(u3, hu3, lu3)

        aH[m][0] = pk(vA0, vA1); aH[m][1] = pk(vB0, vB1);
        aH[m][2] = pk(vA2, vA3); aH[m][3] = pk(vB2, vB3);
        aL[m][0] = pk(lA0, lA1); aL[m][1] = pk(lB0, lB1);
        aL[m][2] = pk(lA2, lA3); aL[m][3] = pk(lB2, lB3);
        sH[m][0] = pk(q0, q1);   sH[m][1] = pk(u0, u1);
        sH[m][2] = pk(q2, q3);   sH[m][3] = pk(u2, u3);
        sL[m][0] = pk(lq0, lq1); sL[m][1] = pk(lu0, lu1);
        sL[m][2] = pk(lq2, lq3); sL[m][3] = pk(lu2, lu3);
    }

    // ---- loop-invariant addresses ----
    const uint32_t wbuf = sbase + (uint32_t)w * WBUF_BYTES;
    // STS: band row 2i, pixel column g (banks 8i+g+c, conflict-free)
    const uint32_t st_b = wbuf + ((uint32_t)(2 * i) * PITCH_W + g) * 4;
    // LDS-back: lane t reads band row (t>>4), 4 px at (t&15)*4
    const uint32_t ld_b = wbuf + (uint32_t)(t >> 4) * (PITCH_W * 4) + (t & 15) * 16;
    // STG: band (t>>4) + 2 per round, pixel pxw + (t&15)*4
    float* gp = out + (size_t)(t >> 4) * NPIX + pxw + (t & 15) * 4;

#pragma unroll 1
    for (int o = 0; o < NOCT; o++) {
        // B fragments from global (coalesced 512B, L1-hit after first pass)
        const uint4 ue = __ldg(&g_tbl[0][o][t]);
        const uint4 uf = __ldg(&g_tbl[1][o][t]);

#pragma unroll
        for (int m = 0; m < 4; m++) {
            float cl0 = 0.f, cl1 = 0.f, cl2 = 0.f, cl3 = 0.f;
            float cq0 = 0.f, cq1 = 0.f, cq2 = 0.f, cq3 = 0.f;
            MMA(cl0, cl1, cl2, cl3, aH[m][0], aH[m][1], aH[m][2], aH[m][3], ue.x, ue.y);
            MMA(cl0, cl1, cl2, cl3, aL[m][0], aL[m][1], aL[m][2], aL[m][3], ue.x, ue.y);
            MMA(cl0, cl1, cl2, cl3, aH[m][0], aH[m][1], aH[m][2], aH[m][3], ue.z, ue.w);
            MMA(cq0, cq1, cq2, cq3, sH[m][0], sH[m][1], sH[m][2], sH[m][3], uf.x, uf.y);
            MMA(cq0, cq1, cq2, cq3, sL[m][0], sL[m][1], sL[m][2], sL[m][3], uf.x, uf.y);
            MMA(cq0, cq1, cq2, cq3, sH[m][0], sH[m][1], sH[m][2], sH[m][3], uf.z, uf.w);

            float r0 = fmaf(0.5f, fmaf(cl0, cl0, -cq0), cl0);  // (band 2i,   px g)
            float r1 = fmaf(0.5f, fmaf(cl1, cl1, -cq1), cl1);  // (band 2i+1, px g)
            float r2 = fmaf(0.5f, fmaf(cl2, cl2, -cq2), cl2);  // (band 2i,   px g+8)
            float r3 = fmaf(0.5f, fmaf(cl3, cl3, -cq3), cl3);  // (band 2i+1, px g+8)

            const uint32_t sb = st_b + m * 64;   // +16 px per tile
            asm volatile("st.shared.f32 [%0], %1;" :: "r"(sb), "f"(r0));
            asm volatile("st.shared.f32 [%0], %1;" :: "r"(sb + PITCH_W * 4), "f"(r1));
            asm volatile("st.shared.f32 [%0], %1;" :: "r"(sb + 32), "f"(r2));
            asm volatile("st.shared.f32 [%0], %1;" :: "r"(sb + PITCH_W * 4 + 32), "f"(r3));
        }
        __syncwarp();

#pragma unroll
        for (int r = 0; r < 4; r++) {
            uint4 q;
            asm("ld.shared.v4.b32 {%0,%1,%2,%3}, [%4];"
                : "=r"(q.x), "=r"(q.y), "=r"(q.z), "=r"(q.w)
                : "r"(ld_b + (uint32_t)r * (2 * PITCH_W * 4)));
            asm volatile("st.global.cs.v4.b32 [%0], {%1,%2,%3,%4};"
                         :: "l"(gp), "r"(q.x), "r"(q.y), "r"(q.z), "r"(q.w)
                         : "memory");
            gp += 2 * (size_t)NPIX;
        }
        __syncwarp();   // buffer reuse guard
    }
}

extern "C" void kernel_launch(void* const* d_in, const int* in_sizes, int n_in,
                              void* d_out, int out_size)
{
    const float* E = (const float*)d_in[0];
    const float* A = (const float*)d_in[1];
    if (in_sizes[0] > in_sizes[1]) {
        E = (const float*)d_in[1];
        A = (const float*)d_in[0];
    }
    float* out = (float*)d_out;

    cudaFuncSetAttribute(fm_mma_kernel,
                         cudaFuncAttributeMaxDynamicSharedMemorySize, SM_TOTAL);

    prep_kernel<<<7, 128>>>(E);
    fm_mma_kernel<<<NPIX / 256, 128, SM_TOTAL>>>(A, out);  // 1024 blocks
}

// round 15
// speedup vs baseline: 1.5887x; 1.1325x over previous
#include <cuda_runtime.h>
#include <cuda_bf16.h>
#include <cstdint>

// Fan-model nonlinear mixing via mma.sync bf16:
//   out[b,x] = L + (L^2 - Q)/2,  L = sum_p E[b,p] a[p,x],  Q = sum_p E^2 a^2
// bf16 hi/lo split, K stacked (al*el dropped).
// R15: 32 px/warp, __ldg B-frags, 7 CTAs/SM (grid 2048 -> 1.98 clean waves),
// double-buffered warp-private transpose with software-pipelined stores:
// LDS of octet o-1 issues before MMA(o) (latency hidden), STG after.

#define NPIX (512 * 512)
#define NP   12
#define NB   224
#define NOCT (NB / 8)            // 28

#define PITCH_W 36                        // floats per band row (32 + 4)
#define WBUF_BYTES (8 * PITCH_W * 4)      // 1152 per slot
#define SM_TOTAL (4 * 2 * WBUF_BYTES)     // 4 warps x 2 slots = 9216

// fragment-order B tables: [mat][octet][lane] = uint4 {b0,b1,lo0,lo1}
__device__ __align__(16) uint4 g_tbl[2][NOCT][32];

static __device__ __forceinline__ uint32_t pk(float lo, float hi) {
    uint32_t r;
    asm("cvt.rn.bf16x2.f32 %0, %1, %2;" : "=r"(r) : "f"(hi), "f"(lo));
    return r;
}

__global__ void prep_kernel(const float* __restrict__ E) {
    int idx = blockIdx.x * blockDim.x + threadIdx.x;
    if (idx >= NOCT * 32) return;
    int o = idx >> 5, t = idx & 31;
    int g = t >> 2, i = t & 3;
    int band = o * 8 + g;

    float eh[16], el[16], fh[16], fl[16];
#pragma unroll
    for (int p = 0; p < 16; p++) {
        float e = (p < NP) ? E[band * NP + p] : 0.0f;
        float f = e * e;
        float ehp = __bfloat162float(__float2bfloat16(e));
        float fhp = __bfloat162float(__float2bfloat16(f));
        eh[p] = e;  el[p] = e - ehp;
        fh[p] = f;  fl[p] = f - fhp;
    }
    uint4 ve, vf;
    ve.x = pk(eh[2 * i], eh[2 * i + 1]);
    ve.y = pk(eh[8 + 2 * i], eh[8 + 2 * i + 1]);
    ve.z = pk(el[2 * i], el[2 * i + 1]);
    ve.w = pk(el[8 + 2 * i], el[8 + 2 * i + 1]);
    vf.x = pk(fh[2 * i], fh[2 * i + 1]);
    vf.y = pk(fh[8 + 2 * i], fh[8 + 2 * i + 1]);
    vf.z = pk(fl[2 * i], fl[2 * i + 1]);
    vf.w = pk(fl[8 + 2 * i], fl[8 + 2 * i + 1]);
    g_tbl[0][o][t] = ve;
    g_tbl[1][o][t] = vf;
}

#define MMA(c0,c1,c2,c3,a0,a1,a2,a3,b0,b1) \
    asm volatile("mma.sync.aligned.m16n8k16.row.col.f32.bf16.bf16.f32 " \
        "{%0,%1,%2,%3}, {%4,%5,%6,%7}, {%8,%9}, {%0,%1,%2,%3};" \
        : "+f"(c0), "+f"(c1), "+f"(c2), "+f"(c3) \
        : "r"(a0), "r"(a1), "r"(a2), "r"(a3), "r"(b0), "r"(b1))

__global__ __launch_bounds__(128, 7) void fm_mma_kernel(
    const float* __restrict__ A, float* __restrict__ out)
{
    extern __shared__ char sm[];
    uint32_t sbase;
    asm("{ .reg .u64 t; cvta.to.shared.u64 t, %1; cvt.u32.u64 %0, t; }"
        : "=r"(sbase) : "l"(sm));

    const int tid = threadIdx.x;
    const int t = tid & 31;
    const int w = tid >> 5;          // warp 0..3
    const int g = t >> 2;            // 0..7
    const int i = t & 3;             // 0..3
    const int pxw = blockIdx.x * 128 + w * 32;   // warp's first pixel

    // ---- A fragments for 2 M-tiles (built once) ----
    uint32_t aH[2][4], aL[2][4], sH[2][4], sL[2][4];
    const int p0 = 2 * i, p1 = 2 * i + 1;
    const int p2 = 2 * i + 8, p3 = 2 * i + 9;
#pragma unroll
    for (int m = 0; m < 2; m++) {
        const int pxA = pxw + 16 * m + g;
        const int pxB = pxA + 8;
        float vA0 = __ldg(A + (size_t)p0 * NPIX + pxA);
        float vA1 = __ldg(A + (size_t)p1 * NPIX + pxA);
        float vB0 = __ldg(A + (size_t)p0 * NPIX + pxB);
        float vB1 = __ldg(A + (size_t)p1 * NPIX + pxB);
        float vA2 = (i < 2) ? __ldg(A + (size_t)p2 * NPIX + pxA) : 0.0f;
        float vA3 = (i < 2) ? __ldg(A + (size_t)p3 * NPIX + pxA) : 0.0f;
        float vB2 = (i < 2) ? __ldg(A + (size_t)p2 * NPIX + pxB) : 0.0f;
        float vB3 = (i < 2) ? __ldg(A + (size_t)p3 * NPIX + pxB) : 0.0f;

#define SPLIT(v, h, l) float h = __bfloat162float(__float2bfloat16(v)); float l = (v) - h;
        SPLIT(vA0, hA0, lA0) SPLIT(vA1, hA1, lA1) SPLIT(vA2, hA2, lA2) SPLIT(vA3, hA3, lA3)
        SPLIT(vB0, hB0, lB0) SPLIT(vB1, hB1, lB1) SPLIT(vB2, hB2, lB2) SPLIT(vB3, hB3, lB3)
        float q0 = vA0 * vA0, q1 = vA1 * vA1, q2 = vA2 * vA2, q3 = vA3 * vA3;
        float u0 = vB0 * vB0, u1 = vB1 * vB1, u2 = vB2 * vB2, u3 = vB3 * vB3;
        SPLIT(q0, hq0, lq0) SPLIT(q1, hq1, lq1) SPLIT(q2, hq2, lq2) SPLIT(q3, hq3, lq3)
        SPLIT(u0, hu0, lu0) SPLIT(u1, hu1, lu1) SPLIT(u2, hu2, lu2) SPLIT(u3, hu3, lu3)

        aH[m][0] = pk(vA0, vA1); aH[m][1] = pk(vB0, vB1);
        aH[m][2] = pk(vA2, vA3); aH[m][3] = pk(vB2, vB3);
        aL[m][0] = pk(lA0, lA1); aL[m][1] = pk(lB0, lB1);
        aL[m][2] = pk(lA2, lA3); aL[m][3] = pk(lB2, lB3);
        sH[m][0] = pk(q0, q1);   sH[m][1] = pk(u0, u1);
        sH[m][2] = pk(q2, q3);   sH[m][3] = pk(u2, u3);
        sL[m][0] = pk(lq0, lq1); sL[m][1] = pk(lu0, lu1);
        sL[m][2] = pk(lq2, lq3); sL[m][3] = pk(lu2, lu3);
    }

    // ---- loop-invariant addresses ----
    const uint32_t wbuf = sbase + (uint32_t)w * (2 * WBUF_BYTES);
    // STS: band row 2i, pixel column g (banks 8i+g, conflict-free)
    const uint32_t st_b = wbuf + ((uint32_t)(2 * i) * PITCH_W + g) * 4;
    // LDS-back: lane t reads band (t>>3), 4 px at (t&7)*4 (+4 bands round 2)
    const uint32_t ld_b = wbuf + (uint32_t)(t >> 3) * (PITCH_W * 4) + (t & 7) * 16;
    // STG: band (t>>3) (+4 round 2), pixel pxw + (t&7)*4
    float* gp = out + (size_t)(t >> 3) * NPIX + pxw + (t & 7) * 4;

    float r[2][4];
#define DO_MMAS(ue, uf) \
    _Pragma("unroll") \
    for (int m = 0; m < 2; m++) { \
        float cl0 = 0.f, cl1 = 0.f, cl2 = 0.f, cl3 = 0.f; \
        float cq0 = 0.f, cq1 = 0.f, cq2 = 0.f, cq3 = 0.f; \
        MMA(cl0, cl1, cl2, cl3, aH[m][0], aH[m][1], aH[m][2], aH[m][3], ue.x, ue.y); \
        MMA(cl0, cl1, cl2, cl3, aL[m][0], aL[m][1], aL[m][2], aL[m][3], ue.x, ue.y); \
        MMA(cl0, cl1, cl2, cl3, aH[m][0], aH[m][1], aH[m][2], aH[m][3], ue.z, ue.w); \
        MMA(cq0, cq1, cq2, cq3, sH[m][0], sH[m][1], sH[m][2], sH[m][3], uf.x, uf.y); \
        MMA(cq0, cq1, cq2, cq3, sL[m][0], sL[m][1], sL[m][2], sL[m][3], uf.x, uf.y); \
        MMA(cq0, cq1, cq2, cq3, sH[m][0], sH[m][1], sH[m][2], sH[m][3], uf.z, uf.w); \
        r[m][0] = fmaf(0.5f, fmaf(cl0, cl0, -cq0), cl0); \
        r[m][1] = fmaf(0.5f, fmaf(cl1, cl1, -cq1), cl1); \
        r[m][2] = fmaf(0.5f, fmaf(cl2, cl2, -cq2), cl2); \
        r[m][3] = fmaf(0.5f, fmaf(cl3, cl3, -cq3), cl3); \
    }

#define DO_STS(so) do { \
    _Pragma("unroll") \
    for (int m = 0; m < 2; m++) { \
        const uint32_t sb = st_b + (so) + m * 64; \
        asm volatile("st.shared.f32 [%0], %1;" :: "r"(sb), "f"(r[m][0])); \
        asm volatile("st.shared.f32 [%0], %1;" :: "r"(sb + PITCH_W * 4), "f"(r[m][1])); \
        asm volatile("st.shared.f32 [%0], %1;" :: "r"(sb + 32), "f"(r[m][2])); \
        asm volatile("st.shared.f32 [%0], %1;" :: "r"(sb + PITCH_W * 4 + 32), "f"(r[m][3])); \
    } \
} while (0)

    // ---- octet 0 (peeled) ----
    {
        const uint4 ue = __ldg(&g_tbl[0][0][t]);
        const uint4 uf = __ldg(&g_tbl[1][0][t]);
        DO_MMAS(ue, uf);
        __syncwarp();
        DO_STS(0u);
        __syncwarp();
    }

#pragma unroll 1
    for (int o = 1; o < NOCT; o++) {
        // LDS of octet o-1 (old slot, data ready; latency hidden under MMAs)
        const uint32_t pso = (uint32_t)((o - 1) & 1) * WBUF_BYTES;
        uint4 q0, q1;
        asm("ld.shared.v4.b32 {%0,%1,%2,%3}, [%4];"
            : "=r"(q0.x), "=r"(q0.y), "=r"(q0.z), "=r"(q0.w)
            : "r"(ld_b + pso));
        asm("ld.shared.v4.b32 {%0,%1,%2,%3}, [%4];"
            : "=r"(q1.x), "=r"(q1.y), "=r"(q1.z), "=r"(q1.w)
            : "r"(ld_b + pso + 4 * PITCH_W * 4));

        const uint4 ue = __ldg(&g_tbl[0][o][t]);
        const uint4 uf = __ldg(&g_tbl[1][o][t]);
        DO_MMAS(ue, uf);

        // store octet o-1 (LDS long since complete)
        asm volatile("st.global.cs.v4.b32 [%0], {%1,%2,%3,%4};"
                     :: "l"(gp), "r"(q0.x), "r"(q0.y), "r"(q0.z), "r"(q0.w)
                     : "memory");
        asm volatile("st.global.cs.v4.b32 [%0], {%1,%2,%3,%4};"
                     :: "l"(gp + 4 * (size_t)NPIX),
                        "r"(q1.x), "r"(q1.y), "r"(q1.z), "r"(q1.w)
                     : "memory");
        gp += 8 * (size_t)NPIX;

        __syncwarp();   // slot(o&1)'s readers (iter o-1) are done
        DO_STS((uint32_t)(o & 1) * WBUF_BYTES);
        __syncwarp();   // STS visible for next iteration's LDS
    }

    // ---- drain octet 27 ----
    {
        const uint32_t pso = (uint32_t)((NOCT - 1) & 1) * WBUF_BYTES;
        uint4 q0, q1;
        asm("ld.shared.v4.b32 {%0,%1,%2,%3}, [%4];"
            : "=r"(q0.x), "=r"(q0.y), "=r"(q0.z), "=r"(q0.w)
            : "r"(ld_b + pso));
        asm("ld.shared.v4.b32 {%0,%1,%2,%3}, [%4];"
            : "=r"(q1.x), "=r"(q1.y), "=r"(q1.z), "=r"(q1.w)
            : "r"(ld_b + pso + 4 * PITCH_W * 4));
        asm volatile("st.global.cs.v4.b32 [%0], {%1,%2,%3,%4};"
                     :: "l"(gp), "r"(q0.x), "r"(q0.y), "r"(q0.z), "r"(q0.w)
                     : "memory");
        asm volatile("st.global.cs.v4.b32 [%0], {%1,%2,%3,%4};"
                     :: "l"(gp + 4 * (size_t)NPIX),
                        "r"(q1.x), "r"(q1.y), "r"(q1.z), "r"(q1.w)
                     : "memory");
    }
}

extern "C" void kernel_launch(void* const* d_in, const int* in_sizes, int n_in,
                              void* d_out, int out_size)
{
    const float* E = (const float*)d_in[0];
    const float* A = (const float*)d_in[1];
    if (in_sizes[0] > in_sizes[1]) {
        E = (const float*)d_in[1];
        A = (const float*)d_in[0];
    }
    float* out = (float*)d_out;

    cudaFuncSetAttribute(fm_mma_kernel,
                         cudaFuncAttributeMaxDynamicSharedMemorySize, SM_TOTAL);

    prep_kernel<<<7, 128>>>(E);
    fm_mma_kernel<<<NPIX / 128, 128, SM_TOTAL>>>(A, out);  // 2048 blocks
}

// round 16
// speedup vs baseline: 1.6040x; 1.0097x over previous
#include <cuda_runtime.h>
#include <cuda_fp16.h>
#include <cstdint>

// Fan-model nonlinear mixing via mma.sync fp16 (R15 lineage):
//   out[b,x] = L + (L^2 - Q)/2,  L = sum_p E[b,p] a[p,x],  Q = sum_p E^2 a^2
// fp16 (10-bit mantissa): L = ah*eh + al*eh + ah*el (3 MMA, err ~2^-22),
// Q = sh*fh (1 MMA, err ~2^-10 on a term worth ~10% of out -> ~1e-4).
// R16 = R15 geometry (32 px/warp, 7 CTAs/SM, 1.98 waves, double-buffered
// warp-private transpose, pipelined stores) with 4 MMAs/tile instead of 6.

#define NPIX (512 * 512)
#define NP   12
#define NB   224
#define NOCT (NB / 8)            // 28

#define PITCH_W 36                        // floats per band row (32 + 4)
#define WBUF_BYTES (8 * PITCH_W * 4)      // 1152 per slot
#define SM_TOTAL (4 * 2 * WBUF_BYTES)     // 9216

// fragment-order B tables: E -> uint4 {eh_klo, eh_khi, el_klo, el_khi},
//                          F -> uint2 {fh_klo, fh_khi}
__device__ __align__(16) uint4 g_tblE[NOCT][32];
__device__ __align__(8)  uint2 g_tblF[NOCT][32];

static __device__ __forceinline__ uint32_t pk16(float lo, float hi) {
    uint32_t r;   // {lo -> low half, hi -> high half}, fp16
    asm("cvt.rn.f16x2.f32 %0, %1, %2;" : "=r"(r) : "f"(hi), "f"(lo));
    return r;
}

__global__ void prep_kernel(const float* __restrict__ E) {
    int idx = blockIdx.x * blockDim.x + threadIdx.x;
    if (idx >= NOCT * 32) return;
    int o = idx >> 5, t = idx & 31;
    int g = t >> 2, i = t & 3;
    int band = o * 8 + g;

    float eh[16], el[16], fh[16];
#pragma unroll
    for (int p = 0; p < 16; p++) {
        float e = (p < NP) ? E[band * NP + p] : 0.0f;
        float f = e * e;
        float ehp = __half2float(__float2half_rn(e));
        eh[p] = e;  el[p] = e - ehp;   // pk16 rounds eh[p] itself
        fh[p] = f;
    }
    uint4 ve;
    ve.x = pk16(eh[2 * i], eh[2 * i + 1]);
    ve.y = pk16(eh[8 + 2 * i], eh[8 + 2 * i + 1]);
    ve.z = pk16(el[2 * i], el[2 * i + 1]);
    ve.w = pk16(el[8 + 2 * i], el[8 + 2 * i + 1]);
    uint2 vf;
    vf.x = pk16(fh[2 * i], fh[2 * i + 1]);
    vf.y = pk16(fh[8 + 2 * i], fh[8 + 2 * i + 1]);
    g_tblE[o][t] = ve;
    g_tblF[o][t] = vf;
}

#define MMA(c0,c1,c2,c3,a0,a1,a2,a3,b0,b1) \
    asm volatile("mma.sync.aligned.m16n8k16.row.col.f32.f16.f16.f32 " \
        "{%0,%1,%2,%3}, {%4,%5,%6,%7}, {%8,%9}, {%0,%1,%2,%3};" \
        : "+f"(c0), "+f"(c1), "+f"(c2), "+f"(c3) \
        : "r"(a0), "r"(a1), "r"(a2), "r"(a3), "r"(b0), "r"(b1))

__global__ __launch_bounds__(128, 7) void fm_mma_kernel(
    const float* __restrict__ A, float* __restrict__ out)
{
    extern __shared__ char sm[];
    uint32_t sbase;
    asm("{ .reg .u64 t; cvta.to.shared.u64 t, %1; cvt.u32.u64 %0, t; }"
        : "=r"(sbase) : "l"(sm));

    const int tid = threadIdx.x;
    const int t = tid & 31;
    const int w = tid >> 5;          // warp 0..3
    const int g = t >> 2;            // 0..7
    const int i = t & 3;             // 0..3
    const int pxw = blockIdx.x * 128 + w * 32;   // warp's first pixel

    // ---- A fragments for 2 M-tiles (built once) ----
    uint32_t aH[2][4], aL[2][4], sH[2][4];
    const int p0 = 2 * i, p1 = 2 * i + 1;
    const int p2 = 2 * i + 8, p3 = 2 * i + 9;
#pragma unroll
    for (int m = 0; m < 2; m++) {
        const int pxA = pxw + 16 * m + g;
        const int pxB = pxA + 8;
        float vA0 = __ldg(A + (size_t)p0 * NPIX + pxA);
        float vA1 = __ldg(A + (size_t)p1 * NPIX + pxA);
        float vB0 = __ldg(A + (size_t)p0 * NPIX + pxB);
        float vB1 = __ldg(A + (size_t)p1 * NPIX + pxB);
        float vA2 = (i < 2) ? __ldg(A + (size_t)p2 * NPIX + pxA) : 0.0f;
        float vA3 = (i < 2) ? __ldg(A + (size_t)p3 * NPIX + pxA) : 0.0f;
        float vB2 = (i < 2) ? __ldg(A + (size_t)p2 * NPIX + pxB) : 0.0f;
        float vB3 = (i < 2) ? __ldg(A + (size_t)p3 * NPIX + pxB) : 0.0f;

#define SPLIT16(v, h, l) \
    float h = __half2float(__float2half_rn(v)); float l = (v) - h;
        SPLIT16(vA0, hA0, lA0) SPLIT16(vA1, hA1, lA1)
        SPLIT16(vA2, hA2, lA2) SPLIT16(vA3, hA3, lA3)
        SPLIT16(vB0, hB0, lB0) SPLIT16(vB1, hB1, lB1)
        SPLIT16(vB2, hB2, lB2) SPLIT16(vB3, hB3, lB3)
        float q0 = vA0 * vA0, q1 = vA1 * vA1, q2 = vA2 * vA2, q3 = vA3 * vA3;
        float u0 = vB0 * vB0, u1 = vB1 * vB1, u2 = vB2 * vB2, u3 = vB3 * vB3;

        aH[m][0] = pk16(vA0, vA1); aH[m][1] = pk16(vB0, vB1);
        aH[m][2] = pk16(vA2, vA3); aH[m][3] = pk16(vB2, vB3);
        aL[m][0] = pk16(lA0, lA1); aL[m][1] = pk16(lB0, lB1);
        aL[m][2] = pk16(lA2, lA3); aL[m][3] = pk16(lB2, lB3);
        sH[m][0] = pk16(q0, q1);   sH[m][1] = pk16(u0, u1);
        sH[m][2] = pk16(q2, q3);   sH[m][3] = pk16(u2, u3);
    }

    // ---- loop-invariant addresses ----
    const uint32_t wbuf = sbase + (uint32_t)w * (2 * WBUF_BYTES);
    const uint32_t st_b = wbuf + ((uint32_t)(2 * i) * PITCH_W + g) * 4;
    const uint32_t ld_b = wbuf + (uint32_t)(t >> 3) * (PITCH_W * 4) + (t & 7) * 16;
    float* gp = out + (size_t)(t >> 3) * NPIX + pxw + (t & 7) * 4;

    float r[2][4];
#define DO_MMAS(ue, uf) \
    _Pragma("unroll") \
    for (int m = 0; m < 2; m++) { \
        float cl0 = 0.f, cl1 = 0.f, cl2 = 0.f, cl3 = 0.f; \
        float cq0 = 0.f, cq1 = 0.f, cq2 = 0.f, cq3 = 0.f; \
        MMA(cl0, cl1, cl2, cl3, aH[m][0], aH[m][1], aH[m][2], aH[m][3], ue.x, ue.y); \
        MMA(cq0, cq1, cq2, cq3, sH[m][0], sH[m][1], sH[m][2], sH[m][3], uf.x, uf.y); \
        MMA(cl0, cl1, cl2, cl3, aL[m][0], aL[m][1], aL[m][2], aL[m][3], ue.x, ue.y); \
        MMA(cl0, cl1, cl2, cl3, aH[m][0], aH[m][1], aH[m][2], aH[m][3], ue.z, ue.w); \
        r[m][0] = fmaf(0.5f, fmaf(cl0, cl0, -cq0), cl0); \
        r[m][1] = fmaf(0.5f, fmaf(cl1, cl1, -cq1), cl1); \
        r[m][2] = fmaf(0.5f, fmaf(cl2, cl2, -cq2), cl2); \
        r[m][3] = fmaf(0.5f, fmaf(cl3, cl3, -cq3), cl3); \
    }

#define DO_STS(so) do { \
    _Pragma("unroll") \
    for (int m = 0; m < 2; m++) { \
        const uint32_t sb = st_b + (so) + m * 64; \
        asm volatile("st.shared.f32 [%0], %1;" :: "r"(sb), "f"(r[m][0])); \
        asm volatile("st.shared.f32 [%0], %1;" :: "r"(sb + PITCH_W * 4), "f"(r[m][1])); \
        asm volatile("st.shared.f32 [%0], %1;" :: "r"(sb + 32), "f"(r[m][2])); \
        asm volatile("st.shared.f32 [%0], %1;" :: "r"(sb + PITCH_W * 4 + 32), "f"(r[m][3])); \
    } \
} while (0)

    // ---- octet 0 (peeled) ----
    {
        const uint4 ue = __ldg(&g_tblE[0][t]);
        const uint2 uf = __ldg(&g_tblF[0][t]);
        DO_MMAS(ue, uf);
        __syncwarp();
        DO_STS(0u);
        __syncwarp();
    }

#pragma unroll 1
    for (int o = 1; o < NOCT; o++) {
        // LDS of octet o-1 (data ready; latency hidden under MMAs)
        const uint32_t pso = (uint32_t)((o - 1) & 1) * WBUF_BYTES;
        uint4 q0, q1;
        asm("ld.shared.v4.b32 {%0,%1,%2,%3}, [%4];"
            : "=r"(q0.x), "=r"(q0.y), "=r"(q0.z), "=r"(q0.w)
            : "r"(ld_b + pso));
        asm("ld.shared.v4.b32 {%0,%1,%2,%3}, [%4];"
            : "=r"(q1.x), "=r"(q1.y), "=r"(q1.z), "=r"(q1.w)
            : "r"(ld_b + pso + 4 * PITCH_W * 4));

        const uint4 ue = __ldg(&g_tblE[o][t]);
        const uint2 uf = __ldg(&g_tblF[o][t]);
        DO_MMAS(ue, uf);

        // store octet o-1 (LDS long since complete)
        asm volatile("st.global.cs.v4.b32 [%0], {%1,%2,%3,%4};"
                     :: "l"(gp), "r"(q0.x), "r"(q0.y), "r"(q0.z), "r"(q0.w)
                     : "memory");
        asm volatile("st.global.cs.v4.b32 [%0], {%1,%2,%3,%4};"
                     :: "l"(gp + 4 * (size_t)NPIX),
                        "r"(q1.x), "r"(q1.y), "r"(q1.z), "r"(q1.w)
                     : "memory");
        gp += 8 * (size_t)NPIX;

        __syncwarp();   // slot(o&1)'s readers (iter o-1) are done
        DO_STS((uint32_t)(o & 1) * WBUF_BYTES);
        __syncwarp();   // STS visible for next iteration's LDS
    }

    // ---- drain octet 27 ----
    {
        const uint32_t pso = (uint32_t)((NOCT - 1) & 1) * WBUF_BYTES;
        uint4 q0, q1;
        asm("ld.shared.v4.b32 {%0,%1,%2,%3}, [%4];"
            : "=r"(q0.x), "=r"(q0.y), "=r"(q0.z), "=r"(q0.w)
            : "r"(ld_b + pso));
        asm("ld.shared.v4.b32 {%0,%1,%2,%3}, [%4];"
            : "=r"(q1.x), "=r"(q1.y), "=r"(q1.z), "=r"(q1.w)
            : "r"(ld_b + pso + 4 * PITCH_W * 4));
        asm volatile("st.global.cs.v4.b32 [%0], {%1,%2,%3,%4};"
                     :: "l"(gp), "r"(q0.x), "r"(q0.y), "r"(q0.z), "r"(q0.w)
                     : "memory");
        asm volatile("st.global.cs.v4.b32 [%0], {%1,%2,%3,%4};"
                     :: "l"(gp + 4 * (size_t)NPIX),
                        "r"(q1.x), "r"(q1.y), "r"(q1.z), "r"(q1.w)
                     : "memory");
    }
}

extern "C" void kernel_launch(void* const* d_in, const int* in_sizes, int n_in,
                              void* d_out, int out_size)
{
    const float* E = (const float*)d_in[0];
    const float* A = (const float*)d_in[1];
    if (in_sizes[0] > in_sizes[1]) {
        E = (const float*)d_in[1];
        A = (const float*)d_in[0];
    }
    float* out = (float*)d_out;

    cudaFuncSetAttribute(fm_mma_kernel,
                         cudaFuncAttributeMaxDynamicSharedMemorySize, SM_TOTAL);

    prep_kernel<<<7, 128>>>(E);
    fm_mma_kernel<<<NPIX / 128, 128, SM_TOTAL>>>(A, out);  // 2048 blocks
}

// round 17
// speedup vs baseline: 1.6124x; 1.0052x over previous
#include <cuda_runtime.h>
#include <cuda_fp16.h>
#include <cstdint>

// Fan-model nonlinear mixing via mma.sync fp16 (R16 lineage):
//   out[b,x] = L + (L^2 - Q)/2,  L = sum_p E[b,p] a[p,x],  Q = sum_p E^2 a^2
// fp16 split: L = ah*eh + al*eh + ah*el (3 MMA), Q = sh*fh (1 MMA).
// R17 = R16 + register double-buffered B-fragment prefetch: frags for
// octet o+1 load during octet o's MMA/store phase (no scoreboard stall at
// the MMA head). Tables padded +1 octet to kill the tail branch.

#define NPIX (512 * 512)
#define NP   12
#define NB   224
#define NOCT (NB / 8)            // 28

#define PITCH_W 36                        // floats per band row (32 + 4)
#define WBUF_BYTES (8 * PITCH_W * 4)      // 1152 per slot
#define SM_TOTAL (4 * 2 * WBUF_BYTES)     // 9216

// fragment-order B tables (+1 pad octet for branch-free prefetch):
// E -> uint4 {eh_klo, eh_khi, el_klo, el_khi}, F -> uint2 {fh_klo, fh_khi}
__device__ __align__(16) uint4 g_tblE[NOCT + 1][32];
__device__ __align__(8)  uint2 g_tblF[NOCT + 1][32];

static __device__ __forceinline__ uint32_t pk16(float lo, float hi) {
    uint32_t r;   // {lo -> low half, hi -> high half}, fp16
    asm("cvt.rn.f16x2.f32 %0, %1, %2;" : "=r"(r) : "f"(hi), "f"(lo));
    return r;
}

__global__ void prep_kernel(const float* __restrict__ E) {
    int idx = blockIdx.x * blockDim.x + threadIdx.x;
    if (idx >= (NOCT + 1) * 32) return;
    int o = idx >> 5, t = idx & 31;
    if (o >= NOCT) {              // pad octet: zeros
        g_tblE[o][t] = make_uint4(0, 0, 0, 0);
        g_tblF[o][t] = make_uint2(0, 0);
        return;
    }
    int g = t >> 2, i = t & 3;
    int band = o * 8 + g;

    float eh[16], el[16], fh[16];
#pragma unroll
    for (int p = 0; p < 16; p++) {
        float e = (p < NP) ? E[band * NP + p] : 0.0f;
        float f = e * e;
        float ehp = __half2float(__float2half_rn(e));
        eh[p] = e;  el[p] = e - ehp;
        fh[p] = f;
    }
    uint4 ve;
    ve.x = pk16(eh[2 * i], eh[2 * i + 1]);
    ve.y = pk16(eh[8 + 2 * i], eh[8 + 2 * i + 1]);
    ve.z = pk16(el[2 * i], el[2 * i + 1]);
    ve.w = pk16(el[8 + 2 * i], el[8 + 2 * i + 1]);
    uint2 vf;
    vf.x = pk16(fh[2 * i], fh[2 * i + 1]);
    vf.y = pk16(fh[8 + 2 * i], fh[8 + 2 * i + 1]);
    g_tblE[o][t] = ve;
    g_tblF[o][t] = vf;
}

#define MMA(c0,c1,c2,c3,a0,a1,a2,a3,b0,b1) \
    asm volatile("mma.sync.aligned.m16n8k16.row.col.f32.f16.f16.f32 " \
        "{%0,%1,%2,%3}, {%4,%5,%6,%7}, {%8,%9}, {%0,%1,%2,%3};" \
        : "+f"(c0), "+f"(c1), "+f"(c2), "+f"(c3) \
        : "r"(a0), "r"(a1), "r"(a2), "r"(a3), "r"(b0), "r"(b1))

__global__ __launch_bounds__(128, 7) void fm_mma_kernel(
    const float* __restrict__ A, float* __restrict__ out)
{
    extern __shared__ char sm[];
    uint32_t sbase;
    asm("{ .reg .u64 t; cvta.to.shared.u64 t, %1; cvt.u32.u64 %0, t; }"
        : "=r"(sbase) : "l"(sm));

    const int tid = threadIdx.x;
    const int t = tid & 31;
    const int w = tid >> 5;          // warp 0..3
    const int g = t >> 2;            // 0..7
    const int i = t & 3;             // 0..3
    const int pxw = blockIdx.x * 128 + w * 32;   // warp's first pixel

    // ---- A fragments for 2 M-tiles (built once) ----
    uint32_t aH[2][4], aL[2][4], sH[2][4];
    const int p0 = 2 * i, p1 = 2 * i + 1;
    const int p2 = 2 * i + 8, p3 = 2 * i + 9;
#pragma unroll
    for (int m = 0; m < 2; m++) {
        const int pxA = pxw + 16 * m + g;
        const int pxB = pxA + 8;
        float vA0 = __ldg(A + (size_t)p0 * NPIX + pxA);
        float vA1 = __ldg(A + (size_t)p1 * NPIX + pxA);
        float vB0 = __ldg(A + (size_t)p0 * NPIX + pxB);
        float vB1 = __ldg(A + (size_t)p1 * NPIX + pxB);
        float vA2 = (i < 2) ? __ldg(A + (size_t)p2 * NPIX + pxA) : 0.0f;
        float vA3 = (i < 2) ? __ldg(A + (size_t)p3 * NPIX + pxA) : 0.0f;
        float vB2 = (i < 2) ? __ldg(A + (size_t)p2 * NPIX + pxB) : 0.0f;
        float vB3 = (i < 2) ? __ldg(A + (size_t)p3 * NPIX + pxB) : 0.0f;

#define SPLIT16(v, h, l) \
    float h = __half2float(__float2half_rn(v)); float l = (v) - h;
        SPLIT16(vA0, hA0, lA0) SPLIT16(vA1, hA1, lA1)
        SPLIT16(vA2, hA2, lA2) SPLIT16(vA3, hA3, lA3)
        SPLIT16(vB0, hB0, lB0) SPLIT16(vB1, hB1, lB1)
        SPLIT16(vB2, hB2, lB2) SPLIT16(vB3, hB3, lB3)
        float q0 = vA0 * vA0, q1 = vA1 * vA1, q2 = vA2 * vA2, q3 = vA3 * vA3;
        float u0 = vB0 * vB0, u1 = vB1 * vB1, u2 = vB2 * vB2, u3 = vB3 * vB3;

        aH[m][0] = pk16(vA0, vA1); aH[m][1] = pk16(vB0, vB1);
        aH[m][2] = pk16(vA2, vA3); aH[m][3] = pk16(vB2, vB3);
        aL[m][0] = pk16(lA0, lA1); aL[m][1] = pk16(lB0, lB1);
        aL[m][2] = pk16(lA2, lA3); aL[m][3] = pk16(lB2, lB3);
        sH[m][0] = pk16(q0, q1);   sH[m][1] = pk16(u0, u1);
        sH[m][2] = pk16(q2, q3);   sH[m][3] = pk16(u2, u3);
    }

    // ---- loop-invariant addresses ----
    const uint32_t wbuf = sbase + (uint32_t)w * (2 * WBUF_BYTES);
    const uint32_t st_b = wbuf + ((uint32_t)(2 * i) * PITCH_W + g) * 4;
    const uint32_t ld_b = wbuf + (uint32_t)(t >> 3) * (PITCH_W * 4) + (t & 7) * 16;
    float* gp = out + (size_t)(t >> 3) * NPIX + pxw + (t & 7) * 4;

    float r[2][4];
#define DO_MMAS(ue, uf) \
    _Pragma("unroll") \
    for (int m = 0; m < 2; m++) { \
        float cl0 = 0.f, cl1 = 0.f, cl2 = 0.f, cl3 = 0.f; \
        float cq0 = 0.f, cq1 = 0.f, cq2 = 0.f, cq3 = 0.f; \
        MMA(cl0, cl1, cl2, cl3, aH[m][0], aH[m][1], aH[m][2], aH[m][3], (ue).x, (ue).y); \
        MMA(cq0, cq1, cq2, cq3, sH[m][0], sH[m][1], sH[m][2], sH[m][3], (uf).x, (uf).y); \
        MMA(cl0, cl1, cl2, cl3, aL[m][0], aL[m][1], aL[m][2], aL[m][3], (ue).x, (ue).y); \
        MMA(cl0, cl1, cl2, cl3, aH[m][0], aH[m][1], aH[m][2], aH[m][3], (ue).z, (ue).w); \
        r[m][0] = fmaf(0.5f, fmaf(cl0, cl0, -cq0), cl0); \
        r[m][1] = fmaf(0.5f, fmaf(cl1, cl1, -cq1), cl1); \
        r[m][2] = fmaf(0.5f, fmaf(cl2, cl2, -cq2), cl2); \
        r[m][3] = fmaf(0.5f, fmaf(cl3, cl3, -cq3), cl3); \
    }

#define DO_STS(so) do { \
    _Pragma("unroll") \
    for (int m = 0; m < 2; m++) { \
        const uint32_t sb = st_b + (so) + m * 64; \
        asm volatile("st.shared.f32 [%0], %1;" :: "r"(sb), "f"(r[m][0])); \
        asm volatile("st.shared.f32 [%0], %1;" :: "r"(sb + PITCH_W * 4), "f"(r[m][1])); \
        asm volatile("st.shared.f32 [%0], %1;" :: "r"(sb + 32), "f"(r[m][2])); \
        asm volatile("st.shared.f32 [%0], %1;" :: "r"(sb + PITCH_W * 4 + 32), "f"(r[m][3])); \
    } \
} while (0)

    // ---- octet 0 (peeled): frags loaded, MMA, prefetch octet 1, STS ----
    uint4 ueC = __ldg(&g_tblE[0][t]);
    uint2 ufC = __ldg(&g_tblF[0][t]);
    DO_MMAS(ueC, ufC);
    ueC = __ldg(&g_tblE[1][t]);      // prefetch octet 1
    ufC = __ldg(&g_tblF[1][t]);
    __syncwarp();
    DO_STS(0u);
    __syncwarp();

#pragma unroll 1
    for (int o = 1; o < NOCT; o++) {
        // LDS of octet o-1 (data ready; latency hidden under MMAs)
        const uint32_t pso = (uint32_t)((o - 1) & 1) * WBUF_BYTES;
        uint4 q0, q1;
        asm("ld.shared.v4.b32 {%0,%1,%2,%3}, [%4];"
            : "=r"(q0.x), "=r"(q0.y), "=r"(q0.z), "=r"(q0.w)
            : "r"(ld_b + pso));
        asm("ld.shared.v4.b32 {%0,%1,%2,%3}, [%4];"
            : "=r"(q1.x), "=r"(q1.y), "=r"(q1.z), "=r"(q1.w)
            : "r"(ld_b + pso + 4 * PITCH_W * 4));

        // MMAs consume prefetched frags (no scoreboard stall)
        DO_MMAS(ueC, ufC);

        // prefetch octet o+1 (pad octet for o = NOCT-1; never consumed)
        ueC = __ldg(&g_tblE[o + 1][t]);
        ufC = __ldg(&g_tblF[o + 1][t]);

        // store octet o-1 (LDS long since complete)
        asm volatile("st.global.cs.v4.b32 [%0], {%1,%2,%3,%4};"
                     :: "l"(gp), "r"(q0.x), "r"(q0.y), "r"(q0.z), "r"(q0.w)
                     : "memory");
        asm volatile("st.global.cs.v4.b32 [%0], {%1,%2,%3,%4};"
                     :: "l"(gp + 4 * (size_t)NPIX),
                        "r"(q1.x), "r"(q1.y), "r"(q1.z), "r"(q1.w)
                     : "memory");
        gp += 8 * (size_t)NPIX;

        __syncwarp();   // slot(o&1)'s readers (iter o-1) are done
        DO_STS((uint32_t)(o & 1) * WBUF_BYTES);
        __syncwarp();   // STS visible for next iteration's LDS
    }

    // ---- drain octet 27 ----
    {
        const uint32_t pso = (uint32_t)((NOCT - 1) & 1) * WBUF_BYTES;
        uint4 q0, q1;
        asm("ld.shared.v4.b32 {%0,%1,%2,%3}, [%4];"
            : "=r"(q0.x), "=r"(q0.y), "=r"(q0.z), "=r"(q0.w)
            : "r"(ld_b + pso));
        asm("ld.shared.v4.b32 {%0,%1,%2,%3}, [%4];"
            : "=r"(q1.x), "=r"(q1.y), "=r"(q1.z), "=r"(q1.w)
            : "r"(ld_b + pso + 4 * PITCH_W * 4));
        asm volatile("st.global.cs.v4.b32 [%0], {%1,%2,%3,%4};"
                     :: "l"(gp), "r"(q0.x), "r"(q0.y), "r"(q0.z), "r"(q0.w)
                     : "memory");
        asm volatile("st.global.cs.v4.b32 [%0], {%1,%2,%3,%4};"
                     :: "l"(gp + 4 * (size_t)NPIX),
                        "r"(q1.x), "r"(q1.y), "r"(q1.z), "r"(q1.w)
                     : "memory");
    }
}

extern "C" void kernel_launch(void* const* d_in, const int* in_sizes, int n_in,
                              void* d_out, int out_size)
{
    const float* E = (const float*)d_in[0];
    const float* A = (const float*)d_in[1];
    if (in_sizes[0] > in_sizes[1]) {
        E = (const float*)d_in[1];
        A = (const float*)d_in[0];
    }
    float* out = (float*)d_out;

    cudaFuncSetAttribute(fm_mma_kernel,
                         cudaFuncAttributeMaxDynamicSharedMemorySize, SM_TOTAL);

    prep_kernel<<<8, 128>>>(E);   // covers NOCT+1 octets
    fm_mma_kernel<<<NPIX / 128, 128, SM_TOTAL>>>(A, out);  // 2048 blocks
}